// round 3
// baseline (speedup 1.0000x reference)
#include <cuda_runtime.h>
#include <cuda_bf16.h>
#include <cstdint>

// Problem constants (match reference)
#define HH 480
#define WW 640
#define NPIX (HH * WW)

// Device-global scratch (no allocation allowed)
__device__ float g_P[24];
__device__ unsigned long long g_scr[NPIX];

// ---------------------------------------------------------------------------
// Kernel 1: projection matrices P0 = [K0 | 0], P1 = K1 @ T[:3,:]
// ---------------------------------------------------------------------------
__global__ void setup_P_kernel(const float* __restrict__ K0,
                               const float* __restrict__ K1,
                               const float* __restrict__ T) {
    if (threadIdx.x == 0 && blockIdx.x == 0) {
        for (int i = 0; i < 3; i++) {
            for (int j = 0; j < 4; j++) {
                g_P[i * 4 + j] = (j < 3) ? K0[i * 3 + j] : 0.0f;
                float s = 0.0f;
                for (int k = 0; k < 3; k++) s += K1[i * 3 + k] * T[k * 4 + j];
                g_P[12 + i * 4 + j] = s;
            }
        }
    }
}

// ---------------------------------------------------------------------------
// Kernel 2: clear scatter scratch
// ---------------------------------------------------------------------------
__global__ void clear_scr_kernel() {
    int i = blockIdx.x * blockDim.x + threadIdx.x;
    if (i < NPIX) g_scr[i] = 0ull;
}

// ---------------------------------------------------------------------------
// One-sided (Hestenes) Jacobi rotation on column pair (P,Q) of A, stored
// column-major a[col][row]. ALL pair quantities (app, aqq, apq) computed
// fresh from the live columns — no incremental-norm drift. Rotation is
// skipped when the pair is already numerically orthogonal, so converged
// pairs are never garbage-rotated. v2/v3 = rows 2,3 of accumulated V.
// ---------------------------------------------------------------------------
template <int P, int Q>
__device__ __forceinline__ void osj(float a[4][4], float v2[4], float v3[4]) {
    float apq = a[P][0] * a[Q][0];
    float app = a[P][0] * a[P][0];
    float aqq = a[Q][0] * a[Q][0];
#pragma unroll
    for (int r = 1; r < 4; r++) {
        apq = fmaf(a[P][r], a[Q][r], apq);
        app = fmaf(a[P][r], a[P][r], app);
        aqq = fmaf(a[Q][r], a[Q][r], aqq);
    }
    // Skip if already orthogonal at fp32 resolution (guards late sweeps).
    if (apq * apq > 1e-14f * app * aqq) {
        // Rutishauser: tau=(aqq-app)/(2 apq); t=sgn(tau)/(|tau|+sqrt(1+tau^2))
        float tau = __fdividef(aqq - app, 2.0f * apq);
        float t = __fdividef(1.0f, fabsf(tau) + sqrtf(fmaf(tau, tau, 1.0f)));
        t = (tau >= 0.0f) ? t : -t;
        float c = rsqrtf(fmaf(t, t, 1.0f));
        float s = t * c;

#pragma unroll
        for (int r = 0; r < 4; r++) {
            float ap = a[P][r], aq = a[Q][r];
            a[P][r] = c * ap - s * aq;
            a[Q][r] = s * ap + c * aq;
        }
        {
            float vp = v2[P], vq = v2[Q];
            v2[P] = c * vp - s * vq;
            v2[Q] = s * vp + c * vq;
            vp = v3[P]; vq = v3[Q];
            v3[P] = c * vp - s * vq;
            v3[Q] = s * vp + c * vq;
        }
    }
}

// ---------------------------------------------------------------------------
// Kernel 3: per-point triangulation (one-sided Jacobi SVD of 4x4 A) + scatter
// out layout: [0, NPIX) depth image (finalize), [NPIX, NPIX+N) kp3d
// ---------------------------------------------------------------------------
__global__ __launch_bounds__(256)
void tri_kernel(const float* __restrict__ mconf,
                const float* __restrict__ kp0,
                const float* __restrict__ kp1,
                float* __restrict__ out, int N) {
    int n = blockIdx.x * blockDim.x + threadIdx.x;
    if (n >= N) return;

    float2 p0 = reinterpret_cast<const float2*>(kp0)[n];
    float2 p1 = reinterpret_cast<const float2*>(kp1)[n];
    float conf = mconf[n];

    // A columns: a[col][row]; rows 0,1 from view0 (w=1), rows 2,3 view1 (w=conf)
    float a[4][4];
#pragma unroll
    for (int j = 0; j < 4; j++) {
        float P00 = g_P[0 * 4 + j], P01 = g_P[1 * 4 + j], P02 = g_P[2 * 4 + j];
        float P10 = g_P[12 + 0 * 4 + j], P11 = g_P[12 + 1 * 4 + j],
              P12 = g_P[12 + 2 * 4 + j];
        a[j][0] = fmaf(p0.x, P02, -P00);
        a[j][1] = fmaf(p0.y, P02, -P01);
        a[j][2] = fmaf(p1.x, P12, -P10) * conf;
        a[j][3] = fmaf(p1.y, P12, -P11) * conf;
    }

    // V rows 2 and 3 (V starts as identity)
    float v2[4] = {0.0f, 0.0f, 1.0f, 0.0f};
    float v3[4] = {0.0f, 0.0f, 0.0f, 1.0f};

    // Cyclic one-sided Jacobi, 8 sweeps (fresh Gram entries each rotation)
#pragma unroll
    for (int sweep = 0; sweep < 8; sweep++) {
        osj<0, 1>(a, v2, v3);
        osj<0, 2>(a, v2, v3);
        osj<0, 3>(a, v2, v3);
        osj<1, 2>(a, v2, v3);
        osj<1, 3>(a, v2, v3);
        osj<2, 3>(a, v2, v3);
    }

    // Exact final column norms; argmin -> V column of smallest singular value
    float bestn = 3.4e38f, bv2 = 0.0f, bv3 = 0.0f;
#pragma unroll
    for (int j = 0; j < 4; j++) {
        float s = a[j][0] * a[j][0];
        s = fmaf(a[j][1], a[j][1], s);
        s = fmaf(a[j][2], a[j][2], s);
        s = fmaf(a[j][3], a[j][3], s);
        if (s < bestn) { bestn = s; bv2 = v2[j]; bv3 = v3[j]; }
    }

    // z = v[2]/v[3] (sign cancels). IEEE div; inf/nan collapse to 0 below.
    float z = bv2 / bv3;
    z = fminf(fmaxf(z, -1000.0f), 1000.0f);
    float kp = (z > 0.0f && z < 30.0f) ? z : 0.0f;

    out[NPIX + n] = kp;

    // Last-index-wins deterministic scatter
    int xi = (int)p0.x;
    int yi = (int)p0.y;
    unsigned long long pk =
        ((unsigned long long)(unsigned)(n + 1) << 32) |
        (unsigned long long)__float_as_uint(kp);
    atomicMax(&g_scr[yi * WW + xi], pk);
}

// ---------------------------------------------------------------------------
// Kernel 4: unpack scratch into the depth image portion of out
// ---------------------------------------------------------------------------
__global__ void finalize_kernel(float* __restrict__ out) {
    int i = blockIdx.x * blockDim.x + threadIdx.x;
    if (i < NPIX) {
        unsigned long long p = g_scr[i];
        out[i] = (p != 0ull) ? __uint_as_float((unsigned)p) : 0.0f;
    }
}

// ---------------------------------------------------------------------------
// kernel_launch
// Inputs: T_0to1[16], K0[9], K1[9], mconf[N], mkpts0_f[2N], mkpts1_f[2N],
//         image0[307200], m_bids[N]
// Output: depth0_sparse [307200] ++ kp3d_val [N]
// ---------------------------------------------------------------------------
extern "C" void kernel_launch(void* const* d_in, const int* in_sizes, int n_in,
                              void* d_out, int out_size) {
    const float* T    = (const float*)d_in[0];
    const float* K0   = (const float*)d_in[1];
    const float* K1   = (const float*)d_in[2];
    const float* conf = (const float*)d_in[3];
    const float* kp0  = (const float*)d_in[4];
    const float* kp1  = (const float*)d_in[5];
    float* out = (float*)d_out;
    int N = in_sizes[3];

    setup_P_kernel<<<1, 32>>>(K0, K1, T);
    clear_scr_kernel<<<NPIX / 256, 256>>>();
    tri_kernel<<<(N + 255) / 256, 256>>>(conf, kp0, kp1, out, N);
    finalize_kernel<<<NPIX / 256, 256>>>(out);
}

// round 4
// speedup vs baseline: 1.4113x; 1.4113x over previous
#include <cuda_runtime.h>
#include <cuda_bf16.h>
#include <cstdint>

// Problem constants (match reference)
#define HH 480
#define WW 640
#define NPIX (HH * WW)

// Device-global scratch (no allocation allowed)
__device__ float g_P[24];
__device__ unsigned long long g_scr[NPIX];

// ---------------------------------------------------------------------------
// Kernel 1: projection matrices P0 = [K0 | 0], P1 = K1 @ T[:3,:]
// ---------------------------------------------------------------------------
__global__ void setup_P_kernel(const float* __restrict__ K0,
                               const float* __restrict__ K1,
                               const float* __restrict__ T) {
    if (threadIdx.x == 0 && blockIdx.x == 0) {
        for (int i = 0; i < 3; i++) {
            for (int j = 0; j < 4; j++) {
                g_P[i * 4 + j] = (j < 3) ? K0[i * 3 + j] : 0.0f;
                float s = 0.0f;
                for (int k = 0; k < 3; k++) s += K1[i * 3 + k] * T[k * 4 + j];
                g_P[12 + i * 4 + j] = s;
            }
        }
    }
}

// ---------------------------------------------------------------------------
// Kernel 2: clear scatter scratch
// ---------------------------------------------------------------------------
__global__ void clear_scr_kernel() {
    int i = blockIdx.x * blockDim.x + threadIdx.x;
    if (i < NPIX) g_scr[i] = 0ull;
}

// ---------------------------------------------------------------------------
// One-sided (Hestenes) Jacobi rotation on column pair (P,Q) of A, stored
// column-major a[col][row]. Pair quantities computed fresh from live columns
// (no incremental drift); converged pairs are skipped, never garbage-rotated.
// Scaled angle formula: h = sqrt(u^2 + w^2), t = sgn(u) * w / (|u| + h)
// -> 1 division instead of 2 (shorter MUFU chain than the tau form).
// v2/v3 = rows 2,3 of accumulated V (the only rows the output needs).
// ---------------------------------------------------------------------------
template <int P, int Q>
__device__ __forceinline__ void osj(float a[4][4], float v2[4], float v3[4]) {
    float apq = a[P][0] * a[Q][0];
    float app = a[P][0] * a[P][0];
    float aqq = a[Q][0] * a[Q][0];
#pragma unroll
    for (int r = 1; r < 4; r++) {
        apq = fmaf(a[P][r], a[Q][r], apq);
        app = fmaf(a[P][r], a[P][r], app);
        aqq = fmaf(a[Q][r], a[Q][r], aqq);
    }
    // Skip if already orthogonal at fp32 resolution (guards late sweeps).
    if (apq * apq > 1e-14f * app * aqq) {
        float u = aqq - app;
        float w = 2.0f * apq;
        float r2 = fmaf(u, u, w * w);          // > 0 since w != 0 here
        float h = r2 * rsqrtf(r2);             // sqrt(u^2 + w^2)
        float t = __fdividef(w, fabsf(u) + h); // |t| <= 1
        t = (u >= 0.0f) ? t : -t;
        float c = rsqrtf(fmaf(t, t, 1.0f));
        float s = t * c;

#pragma unroll
        for (int r = 0; r < 4; r++) {
            float ap = a[P][r], aq = a[Q][r];
            a[P][r] = c * ap - s * aq;
            a[Q][r] = s * ap + c * aq;
        }
        {
            float vp = v2[P], vq = v2[Q];
            v2[P] = c * vp - s * vq;
            v2[Q] = s * vp + c * vq;
            vp = v3[P]; vq = v3[Q];
            v3[P] = c * vp - s * vq;
            v3[Q] = s * vp + c * vq;
        }
    }
}

// ---------------------------------------------------------------------------
// Kernel 3: per-point triangulation (one-sided Jacobi SVD of 4x4 A) + scatter
// out layout: [0, NPIX) depth image (finalize), [NPIX, NPIX+N) kp3d
// ---------------------------------------------------------------------------
__global__ __launch_bounds__(256)
void tri_kernel(const float* __restrict__ mconf,
                const float* __restrict__ kp0,
                const float* __restrict__ kp1,
                float* __restrict__ out, int N) {
    int n = blockIdx.x * blockDim.x + threadIdx.x;
    if (n >= N) return;

    float2 p0 = reinterpret_cast<const float2*>(kp0)[n];
    float2 p1 = reinterpret_cast<const float2*>(kp1)[n];
    float conf = mconf[n];

    // A columns: a[col][row]; rows 0,1 from view0 (w=1), rows 2,3 view1 (w=conf)
    float a[4][4];
#pragma unroll
    for (int j = 0; j < 4; j++) {
        float P00 = g_P[0 * 4 + j], P01 = g_P[1 * 4 + j], P02 = g_P[2 * 4 + j];
        float P10 = g_P[12 + 0 * 4 + j], P11 = g_P[12 + 1 * 4 + j],
              P12 = g_P[12 + 2 * 4 + j];
        a[j][0] = fmaf(p0.x, P02, -P00);
        a[j][1] = fmaf(p0.y, P02, -P01);
        a[j][2] = fmaf(p1.x, P12, -P10) * conf;
        a[j][3] = fmaf(p1.y, P12, -P11) * conf;
    }

    // V rows 2 and 3 (V starts as identity)
    float v2[4] = {0.0f, 0.0f, 1.0f, 0.0f};
    float v3[4] = {0.0f, 0.0f, 0.0f, 1.0f};

    // Cyclic one-sided Jacobi, 5 sweeps (quadratic convergence; sweeps 4-5
    // mostly hit the skip guard and only pay the Gram dots)
#pragma unroll
    for (int sweep = 0; sweep < 5; sweep++) {
        osj<0, 1>(a, v2, v3);
        osj<0, 2>(a, v2, v3);
        osj<0, 3>(a, v2, v3);
        osj<1, 2>(a, v2, v3);
        osj<1, 3>(a, v2, v3);
        osj<2, 3>(a, v2, v3);
    }

    // Exact final column norms; argmin -> V column of smallest singular value
    float bestn = 3.4e38f, bv2 = 0.0f, bv3 = 0.0f;
#pragma unroll
    for (int j = 0; j < 4; j++) {
        float s = a[j][0] * a[j][0];
        s = fmaf(a[j][1], a[j][1], s);
        s = fmaf(a[j][2], a[j][2], s);
        s = fmaf(a[j][3], a[j][3], s);
        if (s < bestn) { bestn = s; bv2 = v2[j]; bv3 = v3[j]; }
    }

    // z = v[2]/v[3] (sign cancels). IEEE div; inf/nan collapse to 0 below.
    float z = bv2 / bv3;
    z = fminf(fmaxf(z, -1000.0f), 1000.0f);
    float kp = (z > 0.0f && z < 30.0f) ? z : 0.0f;

    out[NPIX + n] = kp;

    // Last-index-wins deterministic scatter
    int xi = (int)p0.x;
    int yi = (int)p0.y;
    unsigned long long pk =
        ((unsigned long long)(unsigned)(n + 1) << 32) |
        (unsigned long long)__float_as_uint(kp);
    atomicMax(&g_scr[yi * WW + xi], pk);
}

// ---------------------------------------------------------------------------
// Kernel 4: unpack scratch into the depth image portion of out
// ---------------------------------------------------------------------------
__global__ void finalize_kernel(float* __restrict__ out) {
    int i = blockIdx.x * blockDim.x + threadIdx.x;
    if (i < NPIX) {
        unsigned long long p = g_scr[i];
        out[i] = (p != 0ull) ? __uint_as_float((unsigned)p) : 0.0f;
    }
}

// ---------------------------------------------------------------------------
// kernel_launch
// Inputs: T_0to1[16], K0[9], K1[9], mconf[N], mkpts0_f[2N], mkpts1_f[2N],
//         image0[307200], m_bids[N]
// Output: depth0_sparse [307200] ++ kp3d_val [N]
// ---------------------------------------------------------------------------
extern "C" void kernel_launch(void* const* d_in, const int* in_sizes, int n_in,
                              void* d_out, int out_size) {
    const float* T    = (const float*)d_in[0];
    const float* K0   = (const float*)d_in[1];
    const float* K1   = (const float*)d_in[2];
    const float* conf = (const float*)d_in[3];
    const float* kp0  = (const float*)d_in[4];
    const float* kp1  = (const float*)d_in[5];
    float* out = (float*)d_out;
    int N = in_sizes[3];

    setup_P_kernel<<<1, 32>>>(K0, K1, T);
    clear_scr_kernel<<<NPIX / 256, 256>>>();
    tri_kernel<<<(N + 255) / 256, 256>>>(conf, kp0, kp1, out, N);
    finalize_kernel<<<NPIX / 256, 256>>>(out);
}

// round 5
// speedup vs baseline: 1.5634x; 1.1078x over previous
#include <cuda_runtime.h>
#include <cuda_bf16.h>
#include <cstdint>

// Problem constants (match reference)
#define HH 480
#define WW 640
#define NPIX (HH * WW)

// Device-global scratch (no allocation allowed).
// g_scr is zero-initialized at module load; finalize_kernel re-zeroes each
// word after consuming it, so the "scratch is clear" invariant holds at the
// start of every kernel_launch invocation (incl. every graph replay).
__device__ float g_P[24];
__device__ unsigned long long g_scr[NPIX];

// ---------------------------------------------------------------------------
// Kernel 1: projection matrices P0 = [K0 | 0], P1 = K1 @ T[:3,:]
// ---------------------------------------------------------------------------
__global__ void setup_P_kernel(const float* __restrict__ K0,
                               const float* __restrict__ K1,
                               const float* __restrict__ T) {
    if (threadIdx.x == 0 && blockIdx.x == 0) {
        for (int i = 0; i < 3; i++) {
            for (int j = 0; j < 4; j++) {
                g_P[i * 4 + j] = (j < 3) ? K0[i * 3 + j] : 0.0f;
                float s = 0.0f;
                for (int k = 0; k < 3; k++) s += K1[i * 3 + k] * T[k * 4 + j];
                g_P[12 + i * 4 + j] = s;
            }
        }
    }
}

// ---------------------------------------------------------------------------
// One-sided (Hestenes) Jacobi rotation on column pair (P,Q) of A, stored
// column-major a[col][row]. Pair quantities computed fresh from live columns
// (no incremental drift); converged pairs are skipped, never garbage-rotated.
// Scaled angle: h = sqrt(u^2 + w^2), t = sgn(u) * w / (|u| + h)  (1 division).
// v2/v3 = rows 2,3 of accumulated V (the only rows the output needs).
// ---------------------------------------------------------------------------
template <int P, int Q>
__device__ __forceinline__ void osj(float a[4][4], float v2[4], float v3[4]) {
    float apq = a[P][0] * a[Q][0];
    float app = a[P][0] * a[P][0];
    float aqq = a[Q][0] * a[Q][0];
#pragma unroll
    for (int r = 1; r < 4; r++) {
        apq = fmaf(a[P][r], a[Q][r], apq);
        app = fmaf(a[P][r], a[P][r], app);
        aqq = fmaf(a[Q][r], a[Q][r], aqq);
    }
    // Skip if already orthogonal at fp32 resolution (guards late sweeps).
    if (apq * apq > 1e-14f * app * aqq) {
        float u = aqq - app;
        float w = 2.0f * apq;
        float r2 = fmaf(u, u, w * w);          // > 0 since w != 0 here
        float h = r2 * rsqrtf(r2);             // sqrt(u^2 + w^2)
        float t = __fdividef(w, fabsf(u) + h); // |t| <= 1
        t = (u >= 0.0f) ? t : -t;
        float c = rsqrtf(fmaf(t, t, 1.0f));
        float s = t * c;

#pragma unroll
        for (int r = 0; r < 4; r++) {
            float ap = a[P][r], aq = a[Q][r];
            a[P][r] = c * ap - s * aq;
            a[Q][r] = s * ap + c * aq;
        }
        {
            float vp = v2[P], vq = v2[Q];
            v2[P] = c * vp - s * vq;
            v2[Q] = s * vp + c * vq;
            vp = v3[P]; vq = v3[Q];
            v3[P] = c * vp - s * vq;
            v3[Q] = s * vp + c * vq;
        }
    }
}

// ---------------------------------------------------------------------------
// Kernel 2: per-point triangulation (one-sided Jacobi SVD of 4x4 A) + scatter
// out layout: [0, NPIX) depth image (finalize), [NPIX, NPIX+N) kp3d
// ---------------------------------------------------------------------------
__global__ __launch_bounds__(256)
void tri_kernel(const float* __restrict__ mconf,
                const float* __restrict__ kp0,
                const float* __restrict__ kp1,
                float* __restrict__ out, int N) {
    int n = blockIdx.x * blockDim.x + threadIdx.x;
    if (n >= N) return;

    float2 p0 = reinterpret_cast<const float2*>(kp0)[n];
    float2 p1 = reinterpret_cast<const float2*>(kp1)[n];
    float conf = mconf[n];

    // A columns: a[col][row]; rows 0,1 from view0 (w=1), rows 2,3 view1 (w=conf)
    float a[4][4];
#pragma unroll
    for (int j = 0; j < 4; j++) {
        float P00 = g_P[0 * 4 + j], P01 = g_P[1 * 4 + j], P02 = g_P[2 * 4 + j];
        float P10 = g_P[12 + 0 * 4 + j], P11 = g_P[12 + 1 * 4 + j],
              P12 = g_P[12 + 2 * 4 + j];
        a[j][0] = fmaf(p0.x, P02, -P00);
        a[j][1] = fmaf(p0.y, P02, -P01);
        a[j][2] = fmaf(p1.x, P12, -P10) * conf;
        a[j][3] = fmaf(p1.y, P12, -P11) * conf;
    }

    // V rows 2 and 3 (V starts as identity)
    float v2[4] = {0.0f, 0.0f, 1.0f, 0.0f};
    float v3[4] = {0.0f, 0.0f, 0.0f, 1.0f};

    // Cyclic one-sided Jacobi, 4 sweeps (rel_err identical at 5 and 8 sweeps
    // -> convergence complete by ~sweep 4; skip guard covers the tail)
#pragma unroll
    for (int sweep = 0; sweep < 4; sweep++) {
        osj<0, 1>(a, v2, v3);
        osj<0, 2>(a, v2, v3);
        osj<0, 3>(a, v2, v3);
        osj<1, 2>(a, v2, v3);
        osj<1, 3>(a, v2, v3);
        osj<2, 3>(a, v2, v3);
    }

    // Exact final column norms; argmin -> V column of smallest singular value
    float bestn = 3.4e38f, bv2 = 0.0f, bv3 = 0.0f;
#pragma unroll
    for (int j = 0; j < 4; j++) {
        float s = a[j][0] * a[j][0];
        s = fmaf(a[j][1], a[j][1], s);
        s = fmaf(a[j][2], a[j][2], s);
        s = fmaf(a[j][3], a[j][3], s);
        if (s < bestn) { bestn = s; bv2 = v2[j]; bv3 = v3[j]; }
    }

    // z = v[2]/v[3] (sign cancels). IEEE div; inf/nan collapse to 0 below.
    float z = bv2 / bv3;
    z = fminf(fmaxf(z, -1000.0f), 1000.0f);
    float kp = (z > 0.0f && z < 30.0f) ? z : 0.0f;

    out[NPIX + n] = kp;

    // Last-index-wins deterministic scatter
    int xi = (int)p0.x;
    int yi = (int)p0.y;
    unsigned long long pk =
        ((unsigned long long)(unsigned)(n + 1) << 32) |
        (unsigned long long)__float_as_uint(kp);
    atomicMax(&g_scr[yi * WW + xi], pk);
}

// ---------------------------------------------------------------------------
// Kernel 3: unpack scratch into depth image AND reset scratch for next launch
// ---------------------------------------------------------------------------
__global__ void finalize_kernel(float* __restrict__ out) {
    int i = blockIdx.x * blockDim.x + threadIdx.x;
    if (i < NPIX) {
        unsigned long long p = g_scr[i];
        out[i] = (p != 0ull) ? __uint_as_float((unsigned)p) : 0.0f;
        if (p != 0ull) g_scr[i] = 0ull;   // restore clear invariant
    }
}

// ---------------------------------------------------------------------------
// kernel_launch
// Inputs: T_0to1[16], K0[9], K1[9], mconf[N], mkpts0_f[2N], mkpts1_f[2N],
//         image0[307200], m_bids[N]
// Output: depth0_sparse [307200] ++ kp3d_val [N]
// ---------------------------------------------------------------------------
extern "C" void kernel_launch(void* const* d_in, const int* in_sizes, int n_in,
                              void* d_out, int out_size) {
    const float* T    = (const float*)d_in[0];
    const float* K0   = (const float*)d_in[1];
    const float* K1   = (const float*)d_in[2];
    const float* conf = (const float*)d_in[3];
    const float* kp0  = (const float*)d_in[4];
    const float* kp1  = (const float*)d_in[5];
    float* out = (float*)d_out;
    int N = in_sizes[3];

    setup_P_kernel<<<1, 32>>>(K0, K1, T);
    tri_kernel<<<(N + 255) / 256, 256>>>(conf, kp0, kp1, out, N);
    finalize_kernel<<<NPIX / 256, 256>>>(out);
}

// round 8
// speedup vs baseline: 1.7407x; 1.1134x over previous
#include <cuda_runtime.h>
#include <cuda_bf16.h>
#include <cstdint>

// Problem constants (match reference)
#define HH 480
#define WW 640
#define NPIX (HH * WW)

// Device-global scratch (no allocation allowed).
// Zero-initialized at module load; finalize_kernel re-zeroes consumed words,
// so the "clear" invariant holds at the start of every launch/graph replay.
__device__ __align__(16) unsigned long long g_scr[NPIX];

// ---------------------------------------------------------------------------
// One-sided (Hestenes) Jacobi rotation on column pair (P,Q) of A, stored
// column-major a[col][row]. Pair quantities computed fresh from live columns
// (no incremental drift); converged pairs are skipped, never garbage-rotated.
// Scaled angle: h = sqrt(u^2 + w^2), t = sgn(u) * w / (|u| + h)  (1 division).
// v2/v3 = rows 2,3 of accumulated V (the only rows the output needs).
// ---------------------------------------------------------------------------
template <int P, int Q>
__device__ __forceinline__ void osj(float a[4][4], float v2[4], float v3[4]) {
    float apq = a[P][0] * a[Q][0];
    float app = a[P][0] * a[P][0];
    float aqq = a[Q][0] * a[Q][0];
#pragma unroll
    for (int r = 1; r < 4; r++) {
        apq = fmaf(a[P][r], a[Q][r], apq);
        app = fmaf(a[P][r], a[P][r], app);
        aqq = fmaf(a[Q][r], a[Q][r], aqq);
    }
    // Skip if already orthogonal at fp32 resolution (guards late sweeps).
    if (apq * apq > 1e-14f * app * aqq) {
        float u = aqq - app;
        float w = 2.0f * apq;
        float r2 = fmaf(u, u, w * w);          // > 0 since w != 0 here
        float h = r2 * rsqrtf(r2);             // sqrt(u^2 + w^2)
        float t = __fdividef(w, fabsf(u) + h); // |t| <= 1
        t = (u >= 0.0f) ? t : -t;
        float c = rsqrtf(fmaf(t, t, 1.0f));
        float s = t * c;

#pragma unroll
        for (int r = 0; r < 4; r++) {
            float ap = a[P][r], aq = a[Q][r];
            a[P][r] = c * ap - s * aq;
            a[Q][r] = s * ap + c * aq;
        }
        {
            float vp = v2[P], vq = v2[Q];
            v2[P] = c * vp - s * vq;
            v2[Q] = s * vp + c * vq;
            vp = v3[P]; vq = v3[Q];
            v3[P] = c * vp - s * vq;
            v3[Q] = s * vp + c * vq;
        }
    }
}

// ---------------------------------------------------------------------------
// Kernel 1: per-point triangulation (one-sided Jacobi SVD of 4x4 A) + scatter.
// P matrices computed per-block into shared memory (no separate setup kernel).
// out layout: [0, NPIX) depth image (finalize), [NPIX, NPIX+N) kp3d
// ---------------------------------------------------------------------------
__global__ __launch_bounds__(256)
void tri_kernel(const float* __restrict__ K0g,
                const float* __restrict__ K1g,
                const float* __restrict__ Tg,
                const float* __restrict__ mconf,
                const float* __restrict__ kp0,
                const float* __restrict__ kp1,
                float* __restrict__ out, int N) {
    // sP[0..11] = P0 = [K0|0], sP[12..23] = P1 = K1 @ T[:3,:]
    __shared__ float sP[24];
    int tid = threadIdx.x;
    if (tid < 24) {
        int idx = tid;
        int half = idx >= 12;
        int r = (idx - half * 12) / 4;
        int j = idx & 3;
        float v;
        if (!half) {
            v = (j < 3) ? K0g[r * 3 + j] : 0.0f;
        } else {
            v = K1g[r * 3 + 0] * Tg[0 * 4 + j];
            v = fmaf(K1g[r * 3 + 1], Tg[1 * 4 + j], v);
            v = fmaf(K1g[r * 3 + 2], Tg[2 * 4 + j], v);
        }
        sP[idx] = v;
    }
    __syncthreads();

    int n = blockIdx.x * blockDim.x + tid;
    if (n >= N) return;

    float2 p0 = reinterpret_cast<const float2*>(kp0)[n];
    float2 p1 = reinterpret_cast<const float2*>(kp1)[n];
    float conf = mconf[n];

    // A columns: a[col][row]; rows 0,1 from view0 (w=1), rows 2,3 view1 (w=conf)
    float a[4][4];
#pragma unroll
    for (int j = 0; j < 4; j++) {
        float P00 = sP[0 * 4 + j], P01 = sP[1 * 4 + j], P02 = sP[2 * 4 + j];
        float P10 = sP[12 + 0 * 4 + j], P11 = sP[12 + 1 * 4 + j],
              P12 = sP[12 + 2 * 4 + j];
        a[j][0] = fmaf(p0.x, P02, -P00);
        a[j][1] = fmaf(p0.y, P02, -P01);
        a[j][2] = fmaf(p1.x, P12, -P10) * conf;
        a[j][3] = fmaf(p1.y, P12, -P11) * conf;
    }

    // V rows 2 and 3 (V starts as identity)
    float v2[4] = {0.0f, 0.0f, 1.0f, 0.0f};
    float v3[4] = {0.0f, 0.0f, 0.0f, 1.0f};

    // Cyclic one-sided Jacobi, 3 sweeps + skip guard
#pragma unroll
    for (int sweep = 0; sweep < 3; sweep++) {
        osj<0, 1>(a, v2, v3);
        osj<0, 2>(a, v2, v3);
        osj<0, 3>(a, v2, v3);
        osj<1, 2>(a, v2, v3);
        osj<1, 3>(a, v2, v3);
        osj<2, 3>(a, v2, v3);
    }

    // Exact final column norms; argmin -> V column of smallest singular value
    float bestn = 3.4e38f, bv2 = 0.0f, bv3 = 0.0f;
#pragma unroll
    for (int j = 0; j < 4; j++) {
        float s = a[j][0] * a[j][0];
        s = fmaf(a[j][1], a[j][1], s);
        s = fmaf(a[j][2], a[j][2], s);
        s = fmaf(a[j][3], a[j][3], s);
        if (s < bestn) { bestn = s; bv2 = v2[j]; bv3 = v3[j]; }
    }

    // z = v[2]/v[3] (sign cancels). IEEE div; inf/nan collapse to 0 below.
    float z = bv2 / bv3;
    z = fminf(fmaxf(z, -1000.0f), 1000.0f);
    float kp = (z > 0.0f && z < 30.0f) ? z : 0.0f;

    out[NPIX + n] = kp;

    // Last-index-wins deterministic scatter
    int xi = (int)p0.x;
    int yi = (int)p0.y;
    unsigned long long pk =
        ((unsigned long long)(unsigned)(n + 1) << 32) |
        (unsigned long long)__float_as_uint(kp);
    atomicMax(&g_scr[yi * WW + xi], pk);
}

// ---------------------------------------------------------------------------
// Kernel 2: unpack scratch into depth image AND reset scratch for next launch.
// 2 pixels/thread via 16B loads.
// ---------------------------------------------------------------------------
__global__ void finalize_kernel(float* __restrict__ out) {
    int i = blockIdx.x * blockDim.x + threadIdx.x;   // pair index
    if (i < NPIX / 2) {
        ulonglong2 p = reinterpret_cast<ulonglong2*>(g_scr)[i];
        float2 o;
        o.x = (p.x != 0ull) ? __uint_as_float((unsigned)p.x) : 0.0f;
        o.y = (p.y != 0ull) ? __uint_as_float((unsigned)p.y) : 0.0f;
        reinterpret_cast<float2*>(out)[i] = o;
        if (p.x != 0ull) g_scr[2 * i + 0] = 0ull;    // restore clear invariant
        if (p.y != 0ull) g_scr[2 * i + 1] = 0ull;
    }
}

// ---------------------------------------------------------------------------
// kernel_launch
// Inputs: T_0to1[16], K0[9], K1[9], mconf[N], mkpts0_f[2N], mkpts1_f[2N],
//         image0[307200], m_bids[N]
// Output: depth0_sparse [307200] ++ kp3d_val [N]
// ---------------------------------------------------------------------------
extern "C" void kernel_launch(void* const* d_in, const int* in_sizes, int n_in,
                              void* d_out, int out_size) {
    const float* T    = (const float*)d_in[0];
    const float* K0   = (const float*)d_in[1];
    const float* K1   = (const float*)d_in[2];
    const float* conf = (const float*)d_in[3];
    const float* kp0  = (const float*)d_in[4];
    const float* kp1  = (const float*)d_in[5];
    float* out = (float*)d_out;
    int N = in_sizes[3];

    tri_kernel<<<(N + 255) / 256, 256>>>(K0, K1, T, conf, kp0, kp1, out, N);
    finalize_kernel<<<(NPIX / 2 + 255) / 256, 256>>>(out);
}